// round 1
// baseline (speedup 1.0000x reference)
#include <cuda_runtime.h>
#include <math.h>

#define N_SENT      262144
#define N_BAGS      4096
#define HIDDEN      256
#define NUM_CLASSES 53
#define CH          512   // weight chunk (sentences) staged in smem per iteration

// 2 MB scratch for per-sentence logits (hier=2). Static __device__ — no allocs allowed.
__device__ float2 g_logits[N_SENT];

// ---------------------------------------------------------------------------
// K1: per-sentence attention logits. One warp per sentence, 8 floats per lane.
// ---------------------------------------------------------------------------
__global__ __launch_bounds__(256) void logits_kernel(
    const float4* __restrict__ x,      // [N_SENT, 64] as float4
    const float*  __restrict__ e0,     // rel_emb0 [14, 256]
    const float*  __restrict__ e1,     // rel_emb1 [53, 256]
    const int*    __restrict__ rl,     // relation_levels [53, 2]
    const int*    __restrict__ li)     // label_index [N_SENT]
{
    int gw   = (blockIdx.x * blockDim.x + threadIdx.x) >> 5;
    int lane = threadIdx.x & 31;
    if (gw >= N_SENT) return;

    int c  = __ldg(li + gw);
    int l0 = __ldg(rl + 2 * c);
    int l1 = __ldg(rl + 2 * c + 1);

    const float4* xp = x + (size_t)gw * 64 + lane * 2;
    float4 xa = __ldg(xp);
    float4 xb = __ldg(xp + 1);

    const float4* p0 = reinterpret_cast<const float4*>(e0 + l0 * HIDDEN) + lane * 2;
    const float4* p1 = reinterpret_cast<const float4*>(e1 + l1 * HIDDEN) + lane * 2;
    float4 ea = __ldg(p0), eb = __ldg(p0 + 1);
    float4 fa = __ldg(p1), fb = __ldg(p1 + 1);

    float g0 = xa.x * ea.x + xa.y * ea.y + xa.z * ea.z + xa.w * ea.w
             + xb.x * eb.x + xb.y * eb.y + xb.z * eb.z + xb.w * eb.w;
    float g1 = xa.x * fa.x + xa.y * fa.y + xa.z * fa.z + xa.w * fa.w
             + xb.x * fb.x + xb.y * fb.y + xb.z * fb.z + xb.w * fb.w;

    #pragma unroll
    for (int o = 16; o; o >>= 1) {
        g0 += __shfl_xor_sync(0xffffffffu, g0, o);
        g1 += __shfl_xor_sync(0xffffffffu, g1, o);
    }
    if (lane == 0) g_logits[gw] = make_float2(g0, g1);
}

// ---------------------------------------------------------------------------
// K2: one block per bag. Softmax stats -> staged weights -> weighted x sum
//     (thread t owns hidden dim t for both levels) -> fused GEMM epilogue.
// ---------------------------------------------------------------------------
__global__ __launch_bounds__(256) void bag_kernel(
    const float* __restrict__ x,       // [N_SENT, 256]
    const float* __restrict__ disc,    // [53, 512]
    const float* __restrict__ bias,    // [53]
    const int*   __restrict__ scope,   // [N_BAGS + 1]
    float*       __restrict__ out)     // [N_BAGS, 53]
{
    __shared__ float2 s_w[CH];
    __shared__ float  s_red[16];
    __shared__ float  s_re[2 * HIDDEN];

    const int b    = blockIdx.x;
    const int tid  = threadIdx.x;
    const int lane = tid & 31;
    const int warp = tid >> 5;

    const int s0 = __ldg(scope + b);
    const int s1 = __ldg(scope + b + 1);

    // ---- phase 1a: bag max over both levels ----
    float lm0 = -INFINITY, lm1 = -INFINITY;
    for (int j = s0 + tid; j < s1; j += 256) {
        float2 v = g_logits[j];
        lm0 = fmaxf(lm0, v.x);
        lm1 = fmaxf(lm1, v.y);
    }
    #pragma unroll
    for (int o = 16; o; o >>= 1) {
        lm0 = fmaxf(lm0, __shfl_xor_sync(0xffffffffu, lm0, o));
        lm1 = fmaxf(lm1, __shfl_xor_sync(0xffffffffu, lm1, o));
    }
    if (lane == 0) { s_red[warp] = lm0; s_red[8 + warp] = lm1; }
    __syncthreads();
    float m0 = s_red[0], m1 = s_red[8];
    #pragma unroll
    for (int k = 1; k < 8; k++) {
        m0 = fmaxf(m0, s_red[k]);
        m1 = fmaxf(m1, s_red[8 + k]);
    }
    __syncthreads();   // s_red about to be reused

    // ---- phase 1b: sum of exp ----
    float ls0 = 0.f, ls1 = 0.f;
    for (int j = s0 + tid; j < s1; j += 256) {
        float2 v = g_logits[j];
        ls0 += __expf(v.x - m0);
        ls1 += __expf(v.y - m1);
    }
    #pragma unroll
    for (int o = 16; o; o >>= 1) {
        ls0 += __shfl_xor_sync(0xffffffffu, ls0, o);
        ls1 += __shfl_xor_sync(0xffffffffu, ls1, o);
    }
    if (lane == 0) { s_red[warp] = ls0; s_red[8 + warp] = ls1; }
    __syncthreads();
    float sum0 = 0.f, sum1 = 0.f;
    #pragma unroll
    for (int k = 0; k < 8; k++) { sum0 += s_red[k]; sum1 += s_red[8 + k]; }
    float inv0 = 1.0f / sum0;   // empty bag: inf, but chunk loop is a no-op then
    float inv1 = 1.0f / sum1;

    // ---- phase 2: weighted accumulation; thread t owns hidden dim t ----
    float acc0 = 0.f, acc1 = 0.f;
    for (int cs = s0; cs < s1; cs += CH) {
        int cn = min(CH, s1 - cs);
        __syncthreads();   // protect s_w from previous iteration's readers
        for (int j = tid; j < cn; j += 256) {
            float2 v = g_logits[cs + j];
            s_w[j] = make_float2(__expf(v.x - m0) * inv0,
                                 __expf(v.y - m1) * inv1);
        }
        __syncthreads();

        const float* xb = x + (size_t)cs * HIDDEN + tid;
        int j = 0;
        for (; j + 4 <= cn; j += 4) {
            float x0 = __ldg(xb + (size_t)(j + 0) * HIDDEN);
            float x1 = __ldg(xb + (size_t)(j + 1) * HIDDEN);
            float x2 = __ldg(xb + (size_t)(j + 2) * HIDDEN);
            float x3 = __ldg(xb + (size_t)(j + 3) * HIDDEN);
            float2 w0 = s_w[j], w1 = s_w[j + 1], w2 = s_w[j + 2], w3 = s_w[j + 3];
            acc0 += w0.x * x0; acc1 += w0.y * x0;
            acc0 += w1.x * x1; acc1 += w1.y * x1;
            acc0 += w2.x * x2; acc1 += w2.y * x2;
            acc0 += w3.x * x3; acc1 += w3.y * x3;
        }
        for (; j < cn; j++) {
            float xv = __ldg(xb + (size_t)j * HIDDEN);
            float2 w = s_w[j];
            acc0 += w.x * xv; acc1 += w.y * xv;
        }
    }

    // ---- phase 3: fused epilogue GEMM  out[b, r] = <stack_repre, disc[r]> + bias[r]
    __syncthreads();
    s_re[tid]          = acc0;   // repre[b, 0, :]
    s_re[HIDDEN + tid] = acc1;   // repre[b, 1, :]
    __syncthreads();

    for (int r = warp; r < NUM_CLASSES; r += 8) {
        float sum = 0.f;
        #pragma unroll
        for (int k = lane; k < 2 * HIDDEN; k += 32)
            sum += s_re[k] * __ldg(disc + r * (2 * HIDDEN) + k);
        #pragma unroll
        for (int o = 16; o; o >>= 1)
            sum += __shfl_xor_sync(0xffffffffu, sum, o);
        if (lane == 0)
            out[b * NUM_CLASSES + r] = sum + __ldg(bias + r);
    }
}

// ---------------------------------------------------------------------------
extern "C" void kernel_launch(void* const* d_in, const int* in_sizes, int n_in,
                              void* d_out, int out_size)
{
    const float* x    = (const float*)d_in[0];   // [262144, 256]
    const float* e0   = (const float*)d_in[1];   // [14, 256]
    const float* e1   = (const float*)d_in[2];   // [53, 256]
    const float* disc = (const float*)d_in[3];   // [53, 512]
    const float* bias = (const float*)d_in[4];   // [53]
    const int*   rl   = (const int*)d_in[5];     // [53, 2]
    const int*   li   = (const int*)d_in[6];     // [262144]
    const int*   sc   = (const int*)d_in[7];     // [4097]
    float* out = (float*)d_out;                  // [4096, 53]

    // K1: 8 sentences per 256-thread block
    logits_kernel<<<N_SENT / 8, 256>>>((const float4*)x, e0, e1, rl, li);

    // K2: one block per bag
    bag_kernel<<<N_BAGS, 256>>>(x, disc, bias, sc, out);
}